// round 6
// baseline (speedup 1.0000x reference)
#include <cuda_runtime.h>
#include <cuda_bf16.h>

// ---------------- problem constants ----------------
#define BSZ_B 2
#define T_LEN 100
#define N_OBJ 30
#define BT    (BSZ_B * T_LEN)      // 200
#define MROWS (BT * N_OBJ)         // 6000
#define K1    4096                 // feature dim (depth col handled as rank-1)
#define DH1   512
#define DH2   256
#define DFF   512
#define NH    4
#define DHEAD 64

// ---------------- GEMM tiling ----------------
#define TBM 128
#define TBN 64
#define TBK 32
#define LDA_S 36                   // smem A row stride (floats), conflict-free
#define LDB_S 72                   // smem B row stride (floats), conflict-free
#define ASZ (TBM * LDA_S)          // 4608 floats per stage
#define BSZ2 (TBK * LDB_S)         // 2304 floats per stage
#define GEMM_SMEM ((2 * ASZ + 2 * BSZ2) * 4)   // 55296 bytes

// ---------------- scratch (device globals; no runtime alloc) ----------------
__device__ __align__(16) float g_Wc1[(K1 + 1) * DH1];   // W1a - W2a/29 (4097x512)
__device__ __align__(16) float g_Wc2[DH1 * DH2];        // W1b - W2b/29
__device__ __align__(16) float g_S[BT * K1];            // (sum_n x)/29, feature part
__device__ __align__(16) float g_Sdep[BT];              // (sum_n depth)/29
__device__ __align__(16) float g_U1[BT * DH1];
__device__ __align__(16) float g_H1[MROWS * DH1];
__device__ __align__(16) float g_S1[BT * DH1];
__device__ __align__(16) float g_U2[BT * DH2];
__device__ __align__(16) float g_H2[MROWS * DH2];
__device__ __align__(16) float g_gp[BT * DH2];          // pooled g
__device__ __align__(16) float g_q[BT * DH2];
__device__ __align__(16) float g_k[BT * DH2];
__device__ __align__(16) float g_v[BT * DH2];
__device__ __align__(16) float g_att[BT * DH2];
__device__ __align__(16) float g_proj[BT * DH2];
__device__ __align__(16) float g_y[BT * DH2];
__device__ __align__(16) float g_ff1[BT * DFF];
__device__ __align__(16) float g_ff2[BT * DH2];
__device__ __align__(16) float g_z[BT * DH2];

// ---------------- helpers ----------------
__device__ __forceinline__ unsigned f2tf(float f) {
    unsigned u;
    asm("cvt.rna.tf32.f32 %0, %1;" : "=r"(u) : "f"(f));
    return u;
}

__device__ __forceinline__ void mma_tf32(float* d, const unsigned* a, const unsigned* b) {
    asm volatile(
        "mma.sync.aligned.m16n8k8.row.col.f32.tf32.tf32.f32 "
        "{%0,%1,%2,%3}, {%4,%5,%6,%7}, {%8,%9}, {%0,%1,%2,%3};"
        : "+f"(d[0]), "+f"(d[1]), "+f"(d[2]), "+f"(d[3])
        : "r"(a[0]), "r"(a[1]), "r"(a[2]), "r"(a[3]), "r"(b[0]), "r"(b[1]));
}

__device__ __forceinline__ float blocksum256(float v, float* buf) {
    int tid = threadIdx.x;
    buf[tid] = v;
    __syncthreads();
    for (int s = 128; s > 0; s >>= 1) {
        if (tid < s) buf[tid] += buf[tid + s];
        __syncthreads();
    }
    float r = buf[0];
    __syncthreads();
    return r;
}

// ---------------- prep: combined weights ----------------
__global__ void prep_wc(const float* __restrict__ W1a, const float* __restrict__ W2a,
                        const float* __restrict__ W1b, const float* __restrict__ W2b) {
    const float inv = 1.0f / (N_OBJ - 1);
    int stride = gridDim.x * blockDim.x;
    int n1 = (K1 + 1) * DH1;
    for (int i = blockIdx.x * blockDim.x + threadIdx.x; i < n1; i += stride)
        g_Wc1[i] = W1a[i] - W2a[i] * inv;
    int n2 = DH1 * DH2;
    for (int i = blockIdx.x * blockDim.x + threadIdx.x; i < n2; i += stride)
        g_Wc2[i] = W1b[i] - W2b[i] * inv;
}

// ---------------- column sum over the 30 objects of one (b,t) ----------------
__global__ void colsum30(const float* __restrict__ src, int ld, float* __restrict__ out,
                         int cols, float scale) {
    int bt = blockIdx.y;
    int c = blockIdx.x * blockDim.x + threadIdx.x;
    if (c >= cols) return;
    const float* p = src + (size_t)bt * N_OBJ * ld + c;
    float a = 0.f;
#pragma unroll
    for (int n = 0; n < N_OBJ; n++) a += p[(size_t)n * ld];
    out[(size_t)bt * cols + c] = a * scale;
}

__global__ void depsum(const float* __restrict__ dep) {
    int bt = blockIdx.x * blockDim.x + threadIdx.x;
    if (bt < BT) {
        float s = 0.f;
#pragma unroll
        for (int n = 0; n < N_OBJ; n++) s += dep[bt * N_OBJ + n];
        g_Sdep[bt] = s * (1.0f / (N_OBJ - 1));
    }
}

// ---------------- tf32 tensor-core GEMM (C = A[MxK] * B[KxN] + epilogue) ----------------
// epilogue: + rvec[m]*extw[n]  + grp[(m/30)*ldc + n]  + bias[n], optional relu.
// Requirements: K % 32 == 0, N % 64 == 0 (M may be ragged).
__global__ void __launch_bounds__(256)
gemm_tf32(const float* __restrict__ A, int lda,
          const float* __restrict__ B, int ldb,
          float* __restrict__ C, int ldc,
          int M, int N, int K,
          const float* __restrict__ rvec, const float* __restrict__ extw,
          const float* __restrict__ grp, const float* __restrict__ bias,
          int relu) {
    extern __shared__ float smem[];
    float* sA = smem;                // [2][TBM][LDA_S]
    float* sB = smem + 2 * ASZ;      // [2][TBK][LDB_S]

    const int tid = threadIdx.x;
    const int bM = blockIdx.y * TBM;
    const int bN = blockIdx.x * TBN;
    const int warp = tid >> 5, lane = tid & 31;
    const int wm = (warp >> 1) * 32;   // warp M offset within tile (4 warps in M)
    const int wn = (warp & 1) * 32;    // warp N offset within tile (2 warps in N)
    const int qr = lane >> 2, qc = lane & 3;

    float acc[2][4][4];
#pragma unroll
    for (int i = 0; i < 2; i++)
#pragma unroll
        for (int j = 0; j < 4; j++)
#pragma unroll
            for (int e = 0; e < 4; e++) acc[i][j][e] = 0.f;

    const int KT = K / TBK;

    auto stage = [&](int buf, int kt) {
#pragma unroll
        for (int i = 0; i < 4; i++) {         // A: 1024 float4
            int id = tid + 256 * i;
            int r = id >> 3, c4 = id & 7;
            int gm = bM + r;
            int gmc = gm < M ? gm : (M - 1);
            const float* src = A + (size_t)gmc * lda + (size_t)kt * TBK + c4 * 4;
            unsigned dst = (unsigned)__cvta_generic_to_shared(sA + buf * ASZ + r * LDA_S + c4 * 4);
            int sz = (gm < M) ? 16 : 0;
            asm volatile("cp.async.ca.shared.global [%0], [%1], 16, %2;\n"
                         :: "r"(dst), "l"(src), "r"(sz));
        }
#pragma unroll
        for (int i = 0; i < 2; i++) {         // B: 512 float4
            int id = tid + 256 * i;
            int r = id >> 4, c4 = id & 15;
            const float* src = B + (size_t)(kt * TBK + r) * ldb + bN + c4 * 4;
            unsigned dst = (unsigned)__cvta_generic_to_shared(sB + buf * BSZ2 + r * LDB_S + c4 * 4);
            asm volatile("cp.async.ca.shared.global [%0], [%1], 16, 16;\n"
                         :: "r"(dst), "l"(src));
        }
        asm volatile("cp.async.commit_group;\n" ::: "memory");
    };

    stage(0, 0);
    for (int kt = 0; kt < KT; kt++) {
        asm volatile("cp.async.wait_group 0;\n" ::: "memory");
        __syncthreads();
        if (kt + 1 < KT) stage((kt + 1) & 1, kt + 1);

        const float* As = sA + (kt & 1) * ASZ;
        const float* Bs = sB + (kt & 1) * BSZ2;

#pragma unroll
        for (int ks = 0; ks < 4; ks++) {
            const int k0 = ks * 8;
            unsigned af[2][4], bf[4][2];
#pragma unroll
            for (int i = 0; i < 2; i++) {
                int r = wm + i * 16 + qr;
                af[i][0] = f2tf(As[r * LDA_S + k0 + qc]);
                af[i][1] = f2tf(As[(r + 8) * LDA_S + k0 + qc]);
                af[i][2] = f2tf(As[r * LDA_S + k0 + qc + 4]);
                af[i][3] = f2tf(As[(r + 8) * LDA_S + k0 + qc + 4]);
            }
#pragma unroll
            for (int j = 0; j < 4; j++) {
                int c = wn + j * 8 + qr;
                bf[j][0] = f2tf(Bs[(k0 + qc) * LDB_S + c]);
                bf[j][1] = f2tf(Bs[(k0 + qc + 4) * LDB_S + c]);
            }
#pragma unroll
            for (int i = 0; i < 2; i++)
#pragma unroll
                for (int j = 0; j < 4; j++) mma_tf32(acc[i][j], af[i], bf[j]);
        }
    }

    // epilogue
#pragma unroll
    for (int i = 0; i < 2; i++) {
        int m0 = bM + wm + i * 16 + qr;
#pragma unroll
        for (int j = 0; j < 4; j++) {
            int n0 = bN + wn + j * 8 + qc * 2;
#pragma unroll
            for (int r2 = 0; r2 < 2; r2++) {
                int m = m0 + r2 * 8;
                if (m < M) {
#pragma unroll
                    for (int c2 = 0; c2 < 2; c2++) {
                        int n = n0 + c2;
                        float v = acc[i][j][r2 * 2 + c2];
                        if (rvec) v += rvec[m] * extw[n];
                        if (grp)  v += grp[(size_t)(m / N_OBJ) * ldc + n];
                        if (bias) v += bias[n];
                        if (relu) v = fmaxf(v, 0.f);
                        C[(size_t)m * ldc + n] = v;
                    }
                }
            }
        }
    }
}

// ---------------- small fp32 row-matmul: C[m] = A[m] @ B (+bias)(+relu) ----------------
__global__ void rowmm(const float* __restrict__ A, const float* __restrict__ B,
                      float* __restrict__ C, int N, int K,
                      const float* __restrict__ bias, int relu) {
    __shared__ float sa[512];
    int m = blockIdx.x, tid = threadIdx.x;
    for (int k = tid; k < K; k += blockDim.x) sa[k] = A[(size_t)m * K + k];
    __syncthreads();
    for (int n = tid; n < N; n += blockDim.x) {
        float a0 = 0.f, a1 = 0.f, a2 = 0.f, a3 = 0.f;
        for (int k = 0; k < K; k += 4) {
            a0 += sa[k]     * B[(size_t)k * N + n];
            a1 += sa[k + 1] * B[(size_t)(k + 1) * N + n];
            a2 += sa[k + 2] * B[(size_t)(k + 2) * N + n];
            a3 += sa[k + 3] * B[(size_t)(k + 3) * N + n];
        }
        float v = a0 + a1 + a2 + a3 + (bias ? bias[n] : 0.f);
        if (relu) v = fmaxf(v, 0.f);
        C[(size_t)m * N + n] = v;
    }
}

// ---------------- attention: one block per (t, b*NH+h) ----------------
__global__ void attn_kernel(const float* __restrict__ q, const float* __restrict__ k,
                            const float* __restrict__ v, float* __restrict__ o) {
    int t = blockIdx.x;
    int bh = blockIdx.y;
    int b = bh >> 2, h = bh & 3;
    __shared__ float sq[DHEAD];
    __shared__ float sp[128];
    __shared__ float buf[128];
    int tid = threadIdx.x;
    int rowbase = (b * T_LEN + t) * DH2 + h * DHEAD;
    if (tid < DHEAD) sq[tid] = q[rowbase + tid];
    __syncthreads();
    float sc = -1e30f;
    if (tid < T_LEN) {
        const float* kr = k + (b * T_LEN + tid) * DH2 + h * DHEAD;
        float d = 0.f;
#pragma unroll
        for (int j = 0; j < DHEAD; j++) d += sq[j] * kr[j];
        sc = d * 0.125f;   // 1/sqrt(64)
    }
    buf[tid] = sc;
    __syncthreads();
    for (int s = 64; s > 0; s >>= 1) {
        if (tid < s) buf[tid] = fmaxf(buf[tid], buf[tid + s]);
        __syncthreads();
    }
    float mx = buf[0];
    __syncthreads();
    float e = (tid < T_LEN) ? expf(sc - mx) : 0.f;
    buf[tid] = e;
    __syncthreads();
    for (int s = 64; s > 0; s >>= 1) {
        if (tid < s) buf[tid] += buf[tid + s];
        __syncthreads();
    }
    float inv = 1.f / buf[0];
    __syncthreads();
    sp[tid] = e * inv;
    __syncthreads();
    if (tid < DHEAD) {
        float a = 0.f;
        for (int s = 0; s < T_LEN; s++)
            a += sp[s] * v[(b * T_LEN + s) * DH2 + h * DHEAD + tid];
        o[rowbase + tid] = a;
    }
}

// ---------------- LN(x + r) over 256 ----------------
__global__ void ln_add(const float* __restrict__ x, const float* __restrict__ r,
                       const float* __restrict__ gam, const float* __restrict__ bet,
                       float* __restrict__ out) {
    __shared__ float buf[256];
    int m = blockIdx.x, tid = threadIdx.x;
    float v = x[m * DH2 + tid] + r[m * DH2 + tid];
    float mu = blocksum256(v, buf) * (1.f / DH2);
    float d = v - mu;
    float var = blocksum256(d * d, buf) * (1.f / DH2);
    out[m * DH2 + tid] = d * rsqrtf(var + 1e-5f) * gam[tid] + bet[tid];
}

// ---------------- classifier + sigmoid ----------------
__global__ void classify(const float* __restrict__ z, const float* __restrict__ Wc,
                         const float* __restrict__ bc, float* __restrict__ out) {
    __shared__ float buf[256];
    int m = blockIdx.x, tid = threadIdx.x;
    float v = z[m * DH2 + tid] * Wc[tid];
    float s = blocksum256(v, buf);
    if (tid == 0) out[m] = 1.f / (1.f + expf(-(s + bc[0])));
}

__global__ void zerofill(float* __restrict__ p, int n) {
    int i = blockIdx.x * blockDim.x + threadIdx.x;
    if (i < n) p[i] = 0.f;
}

// ---------------- launch ----------------
extern "C" void kernel_launch(void* const* d_in, const int* in_sizes, int n_in,
                              void* d_out, int out_size) {
    const float* feat = (const float*)d_in[0];   // (2,100,30,4096)
    const float* dep  = (const float*)d_in[1];   // (2,100,30,1)
    const float* W1a = (const float*)d_in[2];
    const float* W2a = (const float*)d_in[3];
    const float* b1a = (const float*)d_in[4];
    const float* W1b = (const float*)d_in[5];
    const float* W2b = (const float*)d_in[6];
    const float* b1b = (const float*)d_in[7];
    const float* Wq = (const float*)d_in[8];
    const float* Wk = (const float*)d_in[9];
    const float* Wv = (const float*)d_in[10];
    const float* Wo = (const float*)d_in[11];
    const float* ln1g = (const float*)d_in[12];
    const float* ln1b = (const float*)d_in[13];
    const float* Wf1 = (const float*)d_in[14];
    const float* bf1 = (const float*)d_in[15];
    const float* Wf2 = (const float*)d_in[16];
    const float* bf2 = (const float*)d_in[17];
    const float* ln2g = (const float*)d_in[18];
    const float* ln2b = (const float*)d_in[19];
    const float* Wc = (const float*)d_in[20];
    const float* bc = (const float*)d_in[21];
    float* out = (float*)d_out;

    float *pWc1, *pWc2, *pS, *pSdep, *pU1, *pH1, *pS1, *pU2, *pH2, *pg;
    float *pq, *pk, *pv, *patt, *pproj, *py, *pff1, *pff2, *pz;
    cudaGetSymbolAddress((void**)&pWc1, g_Wc1);
    cudaGetSymbolAddress((void**)&pWc2, g_Wc2);
    cudaGetSymbolAddress((void**)&pS, g_S);
    cudaGetSymbolAddress((void**)&pSdep, g_Sdep);
    cudaGetSymbolAddress((void**)&pU1, g_U1);
    cudaGetSymbolAddress((void**)&pH1, g_H1);
    cudaGetSymbolAddress((void**)&pS1, g_S1);
    cudaGetSymbolAddress((void**)&pU2, g_U2);
    cudaGetSymbolAddress((void**)&pH2, g_H2);
    cudaGetSymbolAddress((void**)&pg, g_gp);
    cudaGetSymbolAddress((void**)&pq, g_q);
    cudaGetSymbolAddress((void**)&pk, g_k);
    cudaGetSymbolAddress((void**)&pv, g_v);
    cudaGetSymbolAddress((void**)&patt, g_att);
    cudaGetSymbolAddress((void**)&pproj, g_proj);
    cudaGetSymbolAddress((void**)&py, g_y);
    cudaGetSymbolAddress((void**)&pff1, g_ff1);
    cudaGetSymbolAddress((void**)&pff2, g_ff2);
    cudaGetSymbolAddress((void**)&pz, g_z);

    cudaFuncSetAttribute((const void*)gemm_tf32,
                         cudaFuncAttributeMaxDynamicSharedMemorySize, GEMM_SMEM);

    // combined weights + neighbor sums
    prep_wc<<<1024, 256>>>(W1a, W2a, W1b, W2b);
    colsum30<<<dim3(K1 / 128, BT), 128>>>(feat, K1, pS, K1, 1.0f / (N_OBJ - 1));
    depsum<<<1, 256>>>(dep);

    // U1 = (S/29) @ W2a  (+ Sdep * W2a[4096] + b1a)
    gemm_tf32<<<dim3(DH1 / TBN, (BT + TBM - 1) / TBM), 256, GEMM_SMEM>>>(
        pS, K1, W2a, DH1, pU1, DH1, BT, DH1, K1,
        pSdep, W2a + (size_t)K1 * DH1, nullptr, b1a, 0);

    // H1 = relu(X @ Wc1 + depth*Wc1[4096] + U1[bt])
    gemm_tf32<<<dim3(DH1 / TBN, (MROWS + TBM - 1) / TBM), 256, GEMM_SMEM>>>(
        feat, K1, pWc1, DH1, pH1, DH1, MROWS, DH1, K1,
        dep, pWc1 + (size_t)K1 * DH1, pU1, nullptr, 1);

    // layer b
    colsum30<<<dim3(DH1 / 128, BT), 128>>>(pH1, DH1, pS1, DH1, 1.0f / (N_OBJ - 1));
    gemm_tf32<<<dim3(DH2 / TBN, (BT + TBM - 1) / TBM), 256, GEMM_SMEM>>>(
        pS1, DH1, W2b, DH2, pU2, DH2, BT, DH2, DH1,
        nullptr, nullptr, nullptr, b1b, 0);
    gemm_tf32<<<dim3(DH2 / TBN, (MROWS + TBM - 1) / TBM), 256, GEMM_SMEM>>>(
        pH1, DH1, pWc2, DH2, pH2, DH2, MROWS, DH2, DH1,
        nullptr, nullptr, pU2, nullptr, 1);

    // pool
    colsum30<<<dim3(DH2 / 128, BT), 128>>>(pH2, DH2, pg, DH2, 1.0f / N_OBJ);

    // transformer
    rowmm<<<BT, 256>>>(pg, Wq, pq, DH2, DH2, nullptr, 0);
    rowmm<<<BT, 256>>>(pg, Wk, pk, DH2, DH2, nullptr, 0);
    rowmm<<<BT, 256>>>(pg, Wv, pv, DH2, DH2, nullptr, 0);
    attn_kernel<<<dim3(T_LEN, BSZ_B * NH), 128>>>(pq, pk, pv, patt);
    rowmm<<<BT, 256>>>(patt, Wo, pproj, DH2, DH2, nullptr, 0);
    ln_add<<<BT, 256>>>(pg, pproj, ln1g, ln1b, py);
    rowmm<<<BT, 256>>>(py, Wf1, pff1, DFF, DH2, bf1, 1);
    rowmm<<<BT, 256>>>(pff1, Wf2, pff2, DH2, DFF, bf2, 0);
    ln_add<<<BT, 256>>>(py, pff2, ln2g, ln2b, pz);

    // output: probs then zero uncertainty
    classify<<<BT, 256>>>(pz, Wc, bc, out);
    if (out_size > BT) {
        int rem = out_size - BT;
        zerofill<<<(rem + 255) / 256, 256>>>(out + BT, rem);
    }
}

// round 7
// speedup vs baseline: 1.1515x; 1.1515x over previous
#include <cuda_runtime.h>
#include <cuda_bf16.h>

// ---------------- problem constants ----------------
#define BSZ_B 2
#define T_LEN 100
#define N_OBJ 30
#define BT    (BSZ_B * T_LEN)      // 200
#define MROWS (BT * N_OBJ)         // 6000
#define K1    4096
#define DH1   512
#define DH2   256
#define DFF   512
#define NH    4
#define DHEAD 64

// ---------------- GEMM tiling ----------------
#define TBM 128
#define TBN 128
#define TBK 32
#define NS  3                       // pipeline stages
#define LDA_S 36                    // smem A row stride (floats)
#define LDB_S 136                   // smem B row stride (floats)
#define ASZ  (TBM * LDA_S)          // 4608 floats / stage
#define BSZT (TBK * LDB_S)          // 4352 floats / stage
#define GEMM_SMEM (NS * (ASZ + BSZT) * 4)   // 107520 bytes

// ---------------- scratch (device globals; no runtime alloc) ----------------
__device__ __align__(16) float g_Wc1[(K1 + 1) * DH1];
__device__ __align__(16) float g_Wc2[DH1 * DH2];
__device__ __align__(16) float g_S[BT * K1];
__device__ __align__(16) float g_Sdep[BT];
__device__ __align__(16) float g_U1[BT * DH1];
__device__ __align__(16) float g_H1[MROWS * DH1];
__device__ __align__(16) float g_S1[BT * DH1];
__device__ __align__(16) float g_U2[BT * DH2];
__device__ __align__(16) float g_H2[MROWS * DH2];
__device__ __align__(16) float g_gp[BT * DH2];
__device__ __align__(16) float g_q[BT * DH2];
__device__ __align__(16) float g_k[BT * DH2];
__device__ __align__(16) float g_v[BT * DH2];
__device__ __align__(16) float g_att[BT * DH2];
__device__ __align__(16) float g_part[8 * 256 * DH1];   // split-K partials (max 4MB)

// ---------------- helpers ----------------
__device__ __forceinline__ unsigned f2tf(float f) {
    unsigned u;
    asm("cvt.rna.tf32.f32 %0, %1;" : "=r"(u) : "f"(f));
    return u;
}

__device__ __forceinline__ void mma_tf32(float* d, const unsigned* a, const unsigned* b) {
    asm volatile(
        "mma.sync.aligned.m16n8k8.row.col.f32.tf32.tf32.f32 "
        "{%0,%1,%2,%3}, {%4,%5,%6,%7}, {%8,%9}, {%0,%1,%2,%3};"
        : "+f"(d[0]), "+f"(d[1]), "+f"(d[2]), "+f"(d[3])
        : "r"(a[0]), "r"(a[1]), "r"(a[2]), "r"(a[3]), "r"(b[0]), "r"(b[1]));
}

__device__ __forceinline__ float blocksum256(float v, float* buf) {
    int tid = threadIdx.x;
    buf[tid] = v;
    __syncthreads();
    for (int s = 128; s > 0; s >>= 1) {
        if (tid < s) buf[tid] += buf[tid + s];
        __syncthreads();
    }
    float r = buf[0];
    __syncthreads();
    return r;
}

// ---------------- prep: combined weights ----------------
__global__ void prep_wc(const float* __restrict__ W1a, const float* __restrict__ W2a,
                        const float* __restrict__ W1b, const float* __restrict__ W2b) {
    const float inv = 1.0f / (N_OBJ - 1);
    int stride = gridDim.x * blockDim.x;
    int n1 = (K1 + 1) * DH1;
    for (int i = blockIdx.x * blockDim.x + threadIdx.x; i < n1; i += stride)
        g_Wc1[i] = W1a[i] - W2a[i] * inv;
    int n2 = DH1 * DH2;
    for (int i = blockIdx.x * blockDim.x + threadIdx.x; i < n2; i += stride)
        g_Wc2[i] = W1b[i] - W2b[i] * inv;
}

// ---------------- column sum over 30 objects ----------------
__global__ void colsum30(const float* __restrict__ src, int ld, float* __restrict__ out,
                         int cols, float scale) {
    int bt = blockIdx.y;
    int c = blockIdx.x * blockDim.x + threadIdx.x;
    if (c >= cols) return;
    const float* p = src + (size_t)bt * N_OBJ * ld + c;
    float a = 0.f;
#pragma unroll
    for (int n = 0; n < N_OBJ; n++) a += p[(size_t)n * ld];
    out[(size_t)bt * cols + c] = a * scale;
}

__global__ void depsum(const float* __restrict__ dep) {
    int bt = blockIdx.x * blockDim.x + threadIdx.x;
    if (bt < BT) {
        float s = 0.f;
#pragma unroll
        for (int n = 0; n < N_OBJ; n++) s += dep[bt * N_OBJ + n];
        g_Sdep[bt] = s * (1.0f / (N_OBJ - 1));
    }
}

// ---------------- tf32 tensor-core GEMM, 3-stage pipeline ----------------
// direct mode (gridDim.z==1): C = A@B + rvec[m]*extw[n] + grp[m/30][n] + bias[n], relu opt.
// split-K (gridDim.z>1): each z writes raw partial to C + z*planeStride (no epilogue).
// Requires K%32==0, N%128==0.
__global__ void __launch_bounds__(256)
gemm_tf32(const float* __restrict__ A, int lda,
          const float* __restrict__ B, int ldb,
          float* __restrict__ C, int ldc, int planeStride,
          int M, int N, int K,
          const float* __restrict__ rvec, const float* __restrict__ extw,
          const float* __restrict__ grp, const float* __restrict__ bias,
          int relu) {
    extern __shared__ float smem[];
    float* sA = smem;                 // [NS][TBM][LDA_S]
    float* sB = smem + NS * ASZ;      // [NS][TBK][LDB_S]

    const int tid = threadIdx.x;
    const int bM = blockIdx.y * TBM;
    const int bN = blockIdx.x * TBN;
    const int warp = tid >> 5, lane = tid & 31;
    const int wm = (warp >> 1) * 32;    // 4 warps in M
    const int wn = (warp & 1) * 64;     // 2 warps in N
    const int qr = lane >> 2, qc = lane & 3;

    float acc[2][8][4];
#pragma unroll
    for (int i = 0; i < 2; i++)
#pragma unroll
        for (int j = 0; j < 8; j++)
#pragma unroll
            for (int e = 0; e < 4; e++) acc[i][j][e] = 0.f;

    const int KTtot = K / TBK;
    int KT = KTtot, kt0 = 0;
    if (gridDim.z > 1) { KT = KTtot / gridDim.z; kt0 = blockIdx.z * KT; }

    auto stage = [&](int buf, int kt) {
#pragma unroll
        for (int i = 0; i < 4; i++) {          // A: 1024 float4
            int id = tid + 256 * i;
            int r = id >> 3, c4 = id & 7;
            int gm = bM + r;
            int gmc = gm < M ? gm : (M - 1);
            const float* src = A + (size_t)gmc * lda + (size_t)kt * TBK + c4 * 4;
            unsigned dst = (unsigned)__cvta_generic_to_shared(sA + buf * ASZ + r * LDA_S + c4 * 4);
            int sz = (gm < M) ? 16 : 0;
            asm volatile("cp.async.cg.shared.global [%0], [%1], 16, %2;\n"
                         :: "r"(dst), "l"(src), "r"(sz));
        }
#pragma unroll
        for (int i = 0; i < 4; i++) {          // B: 1024 float4
            int id = tid + 256 * i;
            int r = id >> 5, c4 = id & 31;
            const float* src = B + (size_t)(kt * TBK + r) * ldb + bN + c4 * 4;
            unsigned dst = (unsigned)__cvta_generic_to_shared(sB + buf * BSZT + r * LDB_S + c4 * 4);
            asm volatile("cp.async.cg.shared.global [%0], [%1], 16, 16;\n"
                         :: "r"(dst), "l"(src));
        }
        asm volatile("cp.async.commit_group;\n" ::: "memory");
    };

    // prologue: NS-1 stages in flight
#pragma unroll
    for (int s = 0; s < NS - 1; s++) {
        if (s < KT) stage(s, kt0 + s);
        else asm volatile("cp.async.commit_group;\n" ::: "memory");
    }

    for (int kt = 0; kt < KT; kt++) {
        asm volatile("cp.async.wait_group %0;\n" :: "n"(NS - 2) : "memory");
        __syncthreads();

        int nk = kt + NS - 1;
        if (nk < KT) stage(nk % NS, kt0 + nk);
        else asm volatile("cp.async.commit_group;\n" ::: "memory");

        const float* As = sA + (kt % NS) * ASZ;
        const float* Bs = sB + (kt % NS) * BSZT;

#pragma unroll
        for (int ks = 0; ks < 4; ks++) {
            const int k0 = ks * 8;
            unsigned af[2][4], bf[8][2];
#pragma unroll
            for (int i = 0; i < 2; i++) {
                int r = wm + i * 16 + qr;
                af[i][0] = f2tf(As[r * LDA_S + k0 + qc]);
                af[i][1] = f2tf(As[(r + 8) * LDA_S + k0 + qc]);
                af[i][2] = f2tf(As[r * LDA_S + k0 + qc + 4]);
                af[i][3] = f2tf(As[(r + 8) * LDA_S + k0 + qc + 4]);
            }
#pragma unroll
            for (int j = 0; j < 8; j++) {
                int c = wn + j * 8 + qr;
                bf[j][0] = f2tf(Bs[(k0 + qc) * LDB_S + c]);
                bf[j][1] = f2tf(Bs[(k0 + qc + 4) * LDB_S + c]);
            }
#pragma unroll
            for (int i = 0; i < 2; i++)
#pragma unroll
                for (int j = 0; j < 8; j++) mma_tf32(acc[i][j], af[i], bf[j]);
        }
    }

    float* Cout = C + (gridDim.z > 1 ? (size_t)blockIdx.z * planeStride : 0);
    const int raw = (gridDim.z > 1);
#pragma unroll
    for (int i = 0; i < 2; i++) {
        int m0 = bM + wm + i * 16 + qr;
#pragma unroll
        for (int j = 0; j < 8; j++) {
            int n0 = bN + wn + j * 8 + qc * 2;
#pragma unroll
            for (int r2 = 0; r2 < 2; r2++) {
                int m = m0 + r2 * 8;
                if (m < M) {
#pragma unroll
                    for (int c2 = 0; c2 < 2; c2++) {
                        int n = n0 + c2;
                        float v = acc[i][j][r2 * 2 + c2];
                        if (!raw) {
                            if (rvec) v += rvec[m] * extw[n];
                            if (grp)  v += grp[(size_t)(m / N_OBJ) * ldc + n];
                            if (bias) v += bias[n];
                            if (relu) v = fmaxf(v, 0.f);
                        }
                        Cout[(size_t)m * ldc + n] = v;
                    }
                }
            }
        }
    }
}

// ---------------- split-K reduce with epilogue ----------------
__global__ void splitk_reduce(const float* __restrict__ part, int planes, int planeStride,
                              float* __restrict__ C, int M, int N,
                              const float* __restrict__ rvec, const float* __restrict__ extw,
                              const float* __restrict__ bias) {
    int idx = blockIdx.x * blockDim.x + threadIdx.x;
    if (idx >= M * N) return;
    int m = idx / N, n = idx - m * N;
    float s = 0.f;
    for (int z = 0; z < planes; z++) s += part[(size_t)z * planeStride + (size_t)m * N + n];
    if (rvec) s += rvec[m] * extw[n];
    if (bias) s += bias[n];
    C[(size_t)m * N + n] = s;
}

// ---------------- fused q/k/v projection (one block per row) ----------------
__global__ void qkv_kernel(const float* __restrict__ g, const float* __restrict__ Wq,
                           const float* __restrict__ Wk, const float* __restrict__ Wv,
                           float* __restrict__ q, float* __restrict__ k,
                           float* __restrict__ v) {
    __shared__ float sg[DH2];
    int m = blockIdx.x, tid = threadIdx.x;
    sg[tid] = g[(size_t)m * DH2 + tid];
    __syncthreads();
    float aq = 0.f, ak = 0.f, av = 0.f;
#pragma unroll 4
    for (int kk = 0; kk < DH2; kk++) {
        float x = sg[kk];
        aq += x * Wq[(size_t)kk * DH2 + tid];
        ak += x * Wk[(size_t)kk * DH2 + tid];
        av += x * Wv[(size_t)kk * DH2 + tid];
    }
    q[(size_t)m * DH2 + tid] = aq;
    k[(size_t)m * DH2 + tid] = ak;
    v[(size_t)m * DH2 + tid] = av;
}

// ---------------- attention: one block per (t, b*NH+h) ----------------
__global__ void attn_kernel(const float* __restrict__ q, const float* __restrict__ k,
                            const float* __restrict__ v, float* __restrict__ o) {
    int t = blockIdx.x;
    int bh = blockIdx.y;
    int b = bh >> 2, h = bh & 3;
    __shared__ float sq[DHEAD];
    __shared__ float sp[128];
    __shared__ float buf[128];
    int tid = threadIdx.x;
    int rowbase = (b * T_LEN + t) * DH2 + h * DHEAD;
    if (tid < DHEAD) sq[tid] = q[rowbase + tid];
    __syncthreads();
    float sc = -1e30f;
    if (tid < T_LEN) {
        const float* kr = k + (b * T_LEN + tid) * DH2 + h * DHEAD;
        float d = 0.f;
#pragma unroll
        for (int j = 0; j < DHEAD; j++) d += sq[j] * kr[j];
        sc = d * 0.125f;
    }
    buf[tid] = sc;
    __syncthreads();
    for (int s = 64; s > 0; s >>= 1) {
        if (tid < s) buf[tid] = fmaxf(buf[tid], buf[tid + s]);
        __syncthreads();
    }
    float mx = buf[0];
    __syncthreads();
    float e = (tid < T_LEN) ? expf(sc - mx) : 0.f;
    buf[tid] = e;
    __syncthreads();
    for (int s = 64; s > 0; s >>= 1) {
        if (tid < s) buf[tid] += buf[tid + s];
        __syncthreads();
    }
    float inv = 1.f / buf[0];
    __syncthreads();
    sp[tid] = e * inv;
    __syncthreads();
    if (tid < DHEAD) {
        float a = 0.f;
        for (int s = 0; s < T_LEN; s++)
            a += sp[s] * v[(b * T_LEN + s) * DH2 + h * DHEAD + tid];
        o[rowbase + tid] = a;
    }
}

// ---------------- fused tail: proj+LN1+FFN+LN2+classifier (block per row) --------
__global__ void tail_kernel(const float* __restrict__ att, const float* __restrict__ g,
                            const float* __restrict__ Wo,
                            const float* __restrict__ ln1g, const float* __restrict__ ln1b,
                            const float* __restrict__ Wf1, const float* __restrict__ bf1,
                            const float* __restrict__ Wf2, const float* __restrict__ bf2,
                            const float* __restrict__ ln2g, const float* __restrict__ ln2b,
                            const float* __restrict__ Wc, const float* __restrict__ bc,
                            float* __restrict__ out) {
    __shared__ float sctx[DH2];
    __shared__ float sy[DH2];
    __shared__ float sff[DFF];
    __shared__ float buf[256];
    int m = blockIdx.x, tid = threadIdx.x;

    sctx[tid] = att[(size_t)m * DH2 + tid];
    __syncthreads();
    // proj = ctx @ Wo
    float p = 0.f;
#pragma unroll 4
    for (int kk = 0; kk < DH2; kk++) p += sctx[kk] * Wo[(size_t)kk * DH2 + tid];
    // y = LN(g + proj)
    float v = g[(size_t)m * DH2 + tid] + p;
    float mu = blocksum256(v, buf) * (1.f / DH2);
    float d = v - mu;
    float var = blocksum256(d * d, buf) * (1.f / DH2);
    float y = d * rsqrtf(var + 1e-5f) * ln1g[tid] + ln1b[tid];
    sy[tid] = y;
    __syncthreads();
    // ff1 = relu(y @ Wf1 + bf1), 512 outputs (2 per thread)
#pragma unroll
    for (int jj = 0; jj < 2; jj++) {
        int j = tid + jj * 256;
        float a = 0.f;
#pragma unroll 4
        for (int kk = 0; kk < DH2; kk++) a += sy[kk] * Wf1[(size_t)kk * DFF + j];
        sff[j] = fmaxf(a + bf1[j], 0.f);
    }
    __syncthreads();
    // ff2 = ff1 @ Wf2 + bf2
    float a2 = 0.f;
#pragma unroll 4
    for (int kk = 0; kk < DFF; kk++) a2 += sff[kk] * Wf2[(size_t)kk * DH2 + tid];
    a2 += bf2[tid];
    // z = LN(y + ff2)
    float v2 = y + a2;
    float mu2 = blocksum256(v2, buf) * (1.f / DH2);
    float d2 = v2 - mu2;
    float var2 = blocksum256(d2 * d2, buf) * (1.f / DH2);
    float z = d2 * rsqrtf(var2 + 1e-5f) * ln2g[tid] + ln2b[tid];
    // classifier + sigmoid
    float s = blocksum256(z * Wc[tid], buf);
    if (tid == 0) out[m] = 1.f / (1.f + expf(-(s + bc[0])));
}

__global__ void zerofill(float* __restrict__ p, int n) {
    int i = blockIdx.x * blockDim.x + threadIdx.x;
    if (i < n) p[i] = 0.f;
}

// ---------------- launch ----------------
extern "C" void kernel_launch(void* const* d_in, const int* in_sizes, int n_in,
                              void* d_out, int out_size) {
    const float* feat = (const float*)d_in[0];
    const float* dep  = (const float*)d_in[1];
    const float* W1a = (const float*)d_in[2];
    const float* W2a = (const float*)d_in[3];
    const float* b1a = (const float*)d_in[4];
    const float* W1b = (const float*)d_in[5];
    const float* W2b = (const float*)d_in[6];
    const float* b1b = (const float*)d_in[7];
    const float* Wq = (const float*)d_in[8];
    const float* Wk = (const float*)d_in[9];
    const float* Wv = (const float*)d_in[10];
    const float* Wo = (const float*)d_in[11];
    const float* ln1g = (const float*)d_in[12];
    const float* ln1b = (const float*)d_in[13];
    const float* Wf1 = (const float*)d_in[14];
    const float* bf1 = (const float*)d_in[15];
    const float* Wf2 = (const float*)d_in[16];
    const float* bf2 = (const float*)d_in[17];
    const float* ln2g = (const float*)d_in[18];
    const float* ln2b = (const float*)d_in[19];
    const float* Wc = (const float*)d_in[20];
    const float* bc = (const float*)d_in[21];
    float* out = (float*)d_out;

    float *pWc1, *pWc2, *pS, *pSdep, *pU1, *pH1, *pS1, *pU2, *pH2, *pg;
    float *pq, *pk, *pv, *patt, *ppart;
    cudaGetSymbolAddress((void**)&pWc1, g_Wc1);
    cudaGetSymbolAddress((void**)&pWc2, g_Wc2);
    cudaGetSymbolAddress((void**)&pS, g_S);
    cudaGetSymbolAddress((void**)&pSdep, g_Sdep);
    cudaGetSymbolAddress((void**)&pU1, g_U1);
    cudaGetSymbolAddress((void**)&pH1, g_H1);
    cudaGetSymbolAddress((void**)&pS1, g_S1);
    cudaGetSymbolAddress((void**)&pU2, g_U2);
    cudaGetSymbolAddress((void**)&pH2, g_H2);
    cudaGetSymbolAddress((void**)&pg, g_gp);
    cudaGetSymbolAddress((void**)&pq, g_q);
    cudaGetSymbolAddress((void**)&pk, g_k);
    cudaGetSymbolAddress((void**)&pv, g_v);
    cudaGetSymbolAddress((void**)&patt, g_att);
    cudaGetSymbolAddress((void**)&ppart, g_part);

    cudaFuncSetAttribute((const void*)gemm_tf32,
                         cudaFuncAttributeMaxDynamicSharedMemorySize, GEMM_SMEM);

    // combined weights + neighbor sums
    prep_wc<<<1024, 256>>>(W1a, W2a, W1b, W2b);
    colsum30<<<dim3(K1 / 128, BT), 128>>>(feat, K1, pS, K1, 1.0f / (N_OBJ - 1));
    depsum<<<1, 256>>>(dep);

    // U1 = (S/29) @ W2a  (split-K=8, then reduce with Sdep rank-1 + b1a)
    {
        int planeStride = 2 * TBM * DH1;   // gridDim.y * TBM rows
        gemm_tf32<<<dim3(DH1 / TBN, 2, 8), 256, GEMM_SMEM>>>(
            pS, K1, W2a, DH1, ppart, DH1, planeStride, BT, DH1, K1,
            nullptr, nullptr, nullptr, nullptr, 0);
        splitk_reduce<<<(BT * DH1 + 255) / 256, 256>>>(
            ppart, 8, planeStride, pU1, BT, DH1,
            pSdep, W2a + (size_t)K1 * DH1, b1a);
    }

    // H1 = relu(X @ Wc1 + depth*Wc1row4096 + U1[bt])
    gemm_tf32<<<dim3(DH1 / TBN, (MROWS + TBM - 1) / TBM, 1), 256, GEMM_SMEM>>>(
        feat, K1, pWc1, DH1, pH1, DH1, 0, MROWS, DH1, K1,
        dep, pWc1 + (size_t)K1 * DH1, pU1, nullptr, 1);

    // layer b
    colsum30<<<dim3(DH1 / 128, BT), 128>>>(pH1, DH1, pS1, DH1, 1.0f / (N_OBJ - 1));
    {
        int planeStride = 2 * TBM * DH2;
        gemm_tf32<<<dim3(DH2 / TBN, 2, 4), 256, GEMM_SMEM>>>(
            pS1, DH1, W2b, DH2, ppart, DH2, planeStride, BT, DH2, DH1,
            nullptr, nullptr, nullptr, nullptr, 0);
        splitk_reduce<<<(BT * DH2 + 255) / 256, 256>>>(
            ppart, 4, planeStride, pU2, BT, DH2, nullptr, nullptr, b1b);
    }
    gemm_tf32<<<dim3(DH2 / TBN, (MROWS + TBM - 1) / TBM, 1), 256, GEMM_SMEM>>>(
        pH1, DH1, pWc2, DH2, pH2, DH2, 0, MROWS, DH2, DH1,
        nullptr, nullptr, pU2, nullptr, 1);

    // pool
    colsum30<<<dim3(DH2 / 128, BT), 128>>>(pH2, DH2, pg, DH2, 1.0f / N_OBJ);

    // transformer (fused)
    qkv_kernel<<<BT, 256>>>(pg, Wq, Wk, Wv, pq, pk, pv);
    attn_kernel<<<dim3(T_LEN, BSZ_B * NH), 128>>>(pq, pk, pv, patt);
    tail_kernel<<<BT, 256>>>(patt, pg, Wo, ln1g, ln1b, Wf1, bf1, Wf2, bf2,
                             ln2g, ln2b, Wc, bc, out);

    // uncertainty = 0 (and any remainder)
    if (out_size > BT) {
        int rem = out_size - BT;
        zerofill<<<(rem + 255) / 256, 256>>>(out + BT, rem);
    }
}

// round 10
// speedup vs baseline: 1.2605x; 1.0947x over previous
#include <cuda_runtime.h>
#include <cuda_bf16.h>

// ---------------- problem constants ----------------
#define BSZ_B 2
#define T_LEN 100
#define N_OBJ 30
#define BT    (BSZ_B * T_LEN)      // 200
#define MROWS (BT * N_OBJ)         // 6000
#define K1    4096
#define DH1   512
#define DH2   256
#define DFF   512
#define NH    4
#define DHEAD 64

// ---------------- GEMM tiling ----------------
#define TBM 128
#define TBN 128
#define TBK 32
#define NS  3                       // pipeline stages
#define LDA_S 36                    // smem A row stride (floats)
#define LDB_S 136                   // smem B row stride (floats)
#define ASZ  (TBM * LDA_S)          // 4608 floats / stage
#define BSZT (TBK * LDB_S)          // 4352 floats / stage
#define GEMM_SMEM (NS * (ASZ + BSZT) * 4)   // 107520 bytes -> 2 CTAs/SM (215KB of 228KB)

// ---------------- scratch (device globals; no runtime alloc) ----------------
__device__ __align__(16) float g_Wc1[(K1 + 1) * DH1];   // tf32(W1a - W2a/29)
__device__ __align__(16) float g_W2ar[(K1 + 1) * DH1];  // tf32(W2a)
__device__ __align__(16) float g_Wc2[DH1 * DH2];        // tf32(W1b - W2b/29)
__device__ __align__(16) float g_W2br[DH1 * DH2];       // tf32(W2b)
__device__ __align__(16) float g_S[BT * K1];
__device__ __align__(16) float g_Sdep[BT];
__device__ __align__(16) float g_U1[BT * DH1];
__device__ __align__(16) float g_H1[MROWS * DH1];
__device__ __align__(16) float g_S1[BT * DH1];
__device__ __align__(16) float g_U2[BT * DH2];
__device__ __align__(16) float g_H2[MROWS * DH2];
__device__ __align__(16) float g_gp[BT * DH2];
__device__ __align__(16) float g_q[BT * DH2];
__device__ __align__(16) float g_k[BT * DH2];
__device__ __align__(16) float g_v[BT * DH2];
__device__ __align__(16) float g_att[BT * DH2];
__device__ __align__(16) float g_part[16 * 256 * DH1];  // split-K partials (8MB)

// ---------------- helpers ----------------
__device__ __forceinline__ unsigned f2tf(float f) {
    unsigned u;
    asm("cvt.rna.tf32.f32 %0, %1;" : "=r"(u) : "f"(f));
    return u;
}

__device__ __forceinline__ void mma_tf32(float* d, const unsigned* a, const unsigned* b) {
    asm volatile(
        "mma.sync.aligned.m16n8k8.row.col.f32.tf32.tf32.f32 "
        "{%0,%1,%2,%3}, {%4,%5,%6,%7}, {%8,%9}, {%0,%1,%2,%3};"
        : "+f"(d[0]), "+f"(d[1]), "+f"(d[2]), "+f"(d[3])
        : "r"(a[0]), "r"(a[1]), "r"(a[2]), "r"(a[3]), "r"(b[0]), "r"(b[1]));
}

__device__ __forceinline__ float blocksum256(float v, float* buf) {
    int tid = threadIdx.x;
    buf[tid] = v;
    __syncthreads();
    for (int s = 128; s > 0; s >>= 1) {
        if (tid < s) buf[tid] += buf[tid + s];
        __syncthreads();
    }
    float r = buf[0];
    __syncthreads();
    return r;
}

// ---------------- prep: combined + tf32-prerounded weights ----------------
__global__ void prep_wc(const float* __restrict__ W1a, const float* __restrict__ W2a,
                        const float* __restrict__ W1b, const float* __restrict__ W2b) {
    const float inv = 1.0f / (N_OBJ - 1);
    int stride = gridDim.x * blockDim.x;
    int n1 = (K1 + 1) * DH1;
    for (int i = blockIdx.x * blockDim.x + threadIdx.x; i < n1; i += stride) {
        float w2 = W2a[i];
        g_Wc1[i]  = __uint_as_float(f2tf(W1a[i] - w2 * inv));
        g_W2ar[i] = __uint_as_float(f2tf(w2));
    }
    int n2 = DH1 * DH2;
    for (int i = blockIdx.x * blockDim.x + threadIdx.x; i < n2; i += stride) {
        float w2 = W2b[i];
        g_Wc2[i]  = __uint_as_float(f2tf(W1b[i] - w2 * inv));
        g_W2br[i] = __uint_as_float(f2tf(w2));
    }
}

// ---------------- column sum over 30 objects (float4 vectorized) ----------------
__global__ void colsum30(const float* __restrict__ src, int ld, float* __restrict__ out,
                         int cols, float scale) {
    int bt = blockIdx.y;
    int c4 = blockIdx.x * blockDim.x + threadIdx.x;   // float4 index
    if (c4 * 4 >= cols) return;
    const float4* p = (const float4*)(src + (size_t)bt * N_OBJ * ld) + c4;
    int ld4 = ld >> 2;
    float4 a = make_float4(0.f, 0.f, 0.f, 0.f);
#pragma unroll
    for (int n = 0; n < N_OBJ; n++) {
        float4 v = p[(size_t)n * ld4];
        a.x += v.x; a.y += v.y; a.z += v.z; a.w += v.w;
    }
    a.x *= scale; a.y *= scale; a.z *= scale; a.w *= scale;
    ((float4*)(out + (size_t)bt * cols))[c4] = a;
}

__global__ void depsum(const float* __restrict__ dep) {
    int bt = blockIdx.x * blockDim.x + threadIdx.x;
    if (bt < BT) {
        float s = 0.f;
#pragma unroll
        for (int n = 0; n < N_OBJ; n++) s += dep[bt * N_OBJ + n];
        g_Sdep[bt] = s * (1.0f / (N_OBJ - 1));
    }
}

// ---------------- tf32 tensor-core GEMM, 3-stage pipeline, 2 CTAs/SM -----------
// B must be pre-rounded to tf32. A is cvt'd in-loop.
// direct (gridDim.z==1): C = A@B + rvec[m]*extw[n] + grp[m/30][n] + bias[n], relu opt.
// split-K (gridDim.z>1): raw partials to C + z*planeStride.
__global__ void __launch_bounds__(256, 2)
gemm_tf32(const float* __restrict__ A, int lda,
          const float* __restrict__ B, int ldb,
          float* __restrict__ C, int ldc, int planeStride,
          int M, int N, int K,
          const float* __restrict__ rvec, const float* __restrict__ extw,
          const float* __restrict__ grp, const float* __restrict__ bias,
          int relu) {
    extern __shared__ float smem[];
    float* sA = smem;                 // [NS][TBM][LDA_S]
    float* sB = smem + NS * ASZ;      // [NS][TBK][LDB_S]

    const int tid = threadIdx.x;
    const int bM = blockIdx.y * TBM;
    const int bN = blockIdx.x * TBN;
    const int warp = tid >> 5, lane = tid & 31;
    const int wm = (warp >> 1) * 32;    // 4 warps in M
    const int wn = (warp & 1) * 64;     // 2 warps in N
    const int qr = lane >> 2, qc = lane & 3;

    float acc[2][8][4];
#pragma unroll
    for (int i = 0; i < 2; i++)
#pragma unroll
        for (int j = 0; j < 8; j++)
#pragma unroll
            for (int e = 0; e < 4; e++) acc[i][j][e] = 0.f;

    const int KTtot = K / TBK;
    int KT = KTtot, kt0 = 0;
    if (gridDim.z > 1) { KT = KTtot / gridDim.z; kt0 = blockIdx.z * KT; }

    auto stage = [&](int buf, int kt) {
#pragma unroll
        for (int i = 0; i < 4; i++) {          // A: 1024 float4
            int id = tid + 256 * i;
            int r = id >> 3, c4 = id & 7;
            int gm = bM + r;
            int gmc = gm < M ? gm : (M - 1);
            const float* src = A + (size_t)gmc * lda + (size_t)kt * TBK + c4 * 4;
            unsigned dst = (unsigned)__cvta_generic_to_shared(sA + buf * ASZ + r * LDA_S + c4 * 4);
            int sz = (gm < M) ? 16 : 0;
            asm volatile("cp.async.cg.shared.global [%0], [%1], 16, %2;\n"
                         :: "r"(dst), "l"(src), "r"(sz));
        }
#pragma unroll
        for (int i = 0; i < 4; i++) {          // B: 1024 float4
            int id = tid + 256 * i;
            int r = id >> 5, c4 = id & 31;
            const float* src = B + (size_t)(kt * TBK + r) * ldb + bN + c4 * 4;
            unsigned dst = (unsigned)__cvta_generic_to_shared(sB + buf * BSZT + r * LDB_S + c4 * 4);
            asm volatile("cp.async.cg.shared.global [%0], [%1], 16, 16;\n"
                         :: "r"(dst), "l"(src));
        }
        asm volatile("cp.async.commit_group;\n" ::: "memory");
    };

#pragma unroll
    for (int s = 0; s < NS - 1; s++) {
        if (s < KT) stage(s, kt0 + s);
        else asm volatile("cp.async.commit_group;\n" ::: "memory");
    }

    for (int kt = 0; kt < KT; kt++) {
        asm volatile("cp.async.wait_group %0;\n" :: "n"(NS - 2) : "memory");
        __syncthreads();

        int nk = kt + NS - 1;
        if (nk < KT) stage(nk % NS, kt0 + nk);
        else asm volatile("cp.async.commit_group;\n" ::: "memory");

        const float* As = sA + (kt % NS) * ASZ;
        const unsigned* Bs = (const unsigned*)(sB + (kt % NS) * BSZT);

#pragma unroll
        for (int ks = 0; ks < 4; ks++) {
            const int k0 = ks * 8;
            unsigned af[2][4], bf[8][2];
#pragma unroll
            for (int i = 0; i < 2; i++) {
                int r = wm + i * 16 + qr;
                af[i][0] = f2tf(As[r * LDA_S + k0 + qc]);
                af[i][1] = f2tf(As[(r + 8) * LDA_S + k0 + qc]);
                af[i][2] = f2tf(As[r * LDA_S + k0 + qc + 4]);
                af[i][3] = f2tf(As[(r + 8) * LDA_S + k0 + qc + 4]);
            }
#pragma unroll
            for (int j = 0; j < 8; j++) {
                int c = wn + j * 8 + qr;
                bf[j][0] = Bs[(k0 + qc) * LDB_S + c];          // pre-rounded tf32
                bf[j][1] = Bs[(k0 + qc + 4) * LDB_S + c];
            }
#pragma unroll
            for (int i = 0; i < 2; i++)
#pragma unroll
                for (int j = 0; j < 8; j++) mma_tf32(acc[i][j], af[i], bf[j]);
        }
    }

    float* Cout = C + (gridDim.z > 1 ? (size_t)blockIdx.z * planeStride : 0);
    const int raw = (gridDim.z > 1);
#pragma unroll
    for (int i = 0; i < 2; i++) {
        int m0 = bM + wm + i * 16 + qr;
#pragma unroll
        for (int j = 0; j < 8; j++) {
            int n0 = bN + wn + j * 8 + qc * 2;
#pragma unroll
            for (int r2 = 0; r2 < 2; r2++) {
                int m = m0 + r2 * 8;
                if (m < M) {
#pragma unroll
                    for (int c2 = 0; c2 < 2; c2++) {
                        int n = n0 + c2;
                        float v = acc[i][j][r2 * 2 + c2];
                        if (!raw) {
                            if (rvec) v += rvec[m] * extw[n];
                            if (grp)  v += grp[(size_t)(m / N_OBJ) * ldc + n];
                            if (bias) v += bias[n];
                            if (relu) v = fmaxf(v, 0.f);
                        }
                        Cout[(size_t)m * ldc + n] = v;
                    }
                }
            }
        }
    }
}

// ---------------- split-K reduce with epilogue ----------------
__global__ void splitk_reduce(const float* __restrict__ part, int planes, int planeStride,
                              float* __restrict__ C, int M, int N,
                              const float* __restrict__ rvec, const float* __restrict__ extw,
                              const float* __restrict__ bias) {
    int idx = blockIdx.x * blockDim.x + threadIdx.x;
    if (idx >= M * N) return;
    int m = idx / N, n = idx - m * N;
    float s = 0.f;
    for (int z = 0; z < planes; z++) s += part[(size_t)z * planeStride + (size_t)m * N + n];
    if (rvec) s += rvec[m] * extw[n];
    if (bias) s += bias[n];
    C[(size_t)m * N + n] = s;
}

// ---------------- fused q/k/v projection ----------------
__global__ void qkv_kernel(const float* __restrict__ g, const float* __restrict__ Wq,
                           const float* __restrict__ Wk, const float* __restrict__ Wv,
                           float* __restrict__ q, float* __restrict__ k,
                           float* __restrict__ v) {
    __shared__ float sg[DH2];
    int m = blockIdx.x, tid = threadIdx.x;
    sg[tid] = g[(size_t)m * DH2 + tid];
    __syncthreads();
    float aq = 0.f, ak = 0.f, av = 0.f;
#pragma unroll 4
    for (int kk = 0; kk < DH2; kk++) {
        float x = sg[kk];
        aq += x * Wq[(size_t)kk * DH2 + tid];
        ak += x * Wk[(size_t)kk * DH2 + tid];
        av += x * Wv[(size_t)kk * DH2 + tid];
    }
    q[(size_t)m * DH2 + tid] = aq;
    k[(size_t)m * DH2 + tid] = ak;
    v[(size_t)m * DH2 + tid] = av;
}

// ---------------- attention ----------------
__global__ void attn_kernel(const float* __restrict__ q, const float* __restrict__ k,
                            const float* __restrict__ v, float* __restrict__ o) {
    int t = blockIdx.x;
    int bh = blockIdx.y;
    int b = bh >> 2, h = bh & 3;
    __shared__ float sq[DHEAD];
    __shared__ float sp[128];
    __shared__ float buf[128];
    int tid = threadIdx.x;
    int rowbase = (b * T_LEN + t) * DH2 + h * DHEAD;
    if (tid < DHEAD) sq[tid] = q[rowbase + tid];
    __syncthreads();
    float sc = -1e30f;
    if (tid < T_LEN) {
        const float* kr = k + (b * T_LEN + tid) * DH2 + h * DHEAD;
        float d = 0.f;
#pragma unroll
        for (int j = 0; j < DHEAD; j++) d += sq[j] * kr[j];
        sc = d * 0.125f;
    }
    buf[tid] = sc;
    __syncthreads();
    for (int s = 64; s > 0; s >>= 1) {
        if (tid < s) buf[tid] = fmaxf(buf[tid], buf[tid + s]);
        __syncthreads();
    }
    float mx = buf[0];
    __syncthreads();
    float e = (tid < T_LEN) ? expf(sc - mx) : 0.f;
    buf[tid] = e;
    __syncthreads();
    for (int s = 64; s > 0; s >>= 1) {
        if (tid < s) buf[tid] += buf[tid + s];
        __syncthreads();
    }
    float inv = 1.f / buf[0];
    __syncthreads();
    sp[tid] = e * inv;
    __syncthreads();
    if (tid < DHEAD) {
        float a = 0.f;
        for (int s = 0; s < T_LEN; s++)
            a += sp[s] * v[(b * T_LEN + s) * DH2 + h * DHEAD + tid];
        o[rowbase + tid] = a;
    }
}

// ---------------- fused tail ----------------
__global__ void tail_kernel(const float* __restrict__ att, const float* __restrict__ g,
                            const float* __restrict__ Wo,
                            const float* __restrict__ ln1g, const float* __restrict__ ln1b,
                            const float* __restrict__ Wf1, const float* __restrict__ bf1,
                            const float* __restrict__ Wf2, const float* __restrict__ bf2,
                            const float* __restrict__ ln2g, const float* __restrict__ ln2b,
                            const float* __restrict__ Wc, const float* __restrict__ bc,
                            float* __restrict__ out) {
    __shared__ float sctx[DH2];
    __shared__ float sy[DH2];
    __shared__ float sff[DFF];
    __shared__ float buf[256];
    int m = blockIdx.x, tid = threadIdx.x;

    sctx[tid] = att[(size_t)m * DH2 + tid];
    __syncthreads();
    float p = 0.f;
#pragma unroll 4
    for (int kk = 0; kk < DH2; kk++) p += sctx[kk] * Wo[(size_t)kk * DH2 + tid];
    float v = g[(size_t)m * DH2 + tid] + p;
    float mu = blocksum256(v, buf) * (1.f / DH2);
    float d = v - mu;
    float var = blocksum256(d * d, buf) * (1.f / DH2);
    float y = d * rsqrtf(var + 1e-5f) * ln1g[tid] + ln1b[tid];
    sy[tid] = y;
    __syncthreads();
#pragma unroll
    for (int jj = 0; jj < 2; jj++) {
        int j = tid + jj * 256;
        float a = 0.f;
#pragma unroll 4
        for (int kk = 0; kk < DH2; kk++) a += sy[kk] * Wf1[(size_t)kk * DFF + j];
        sff[j] = fmaxf(a + bf1[j], 0.f);
    }
    __syncthreads();
    float a2 = 0.f;
#pragma unroll 4
    for (int kk = 0; kk < DFF; kk++) a2 += sff[kk] * Wf2[(size_t)kk * DH2 + tid];
    a2 += bf2[tid];
    float v2 = y + a2;
    float mu2 = blocksum256(v2, buf) * (1.f / DH2);
    float d2 = v2 - mu2;
    float var2 = blocksum256(d2 * d2, buf) * (1.f / DH2);
    float z = d2 * rsqrtf(var2 + 1e-5f) * ln2g[tid] + ln2b[tid];
    float s = blocksum256(z * Wc[tid], buf);
    if (tid == 0) out[m] = 1.f / (1.f + expf(-(s + bc[0])));
}

__global__ void zerofill(float* __restrict__ p, int n) {
    int i = blockIdx.x * blockDim.x + threadIdx.x;
    if (i < n) p[i] = 0.f;
}

// host-side: grid.x for colsum over `cols` floats (float4 per thread, 128 threads)
static inline int cs_grid(int cols) {
    int v = (cols / 4 + 127) / 128;
    return v < 1 ? 1 : v;
}

// ---------------- launch ----------------
extern "C" void kernel_launch(void* const* d_in, const int* in_sizes, int n_in,
                              void* d_out, int out_size) {
    const float* feat = (const float*)d_in[0];
    const float* dep  = (const float*)d_in[1];
    const float* W1a = (const float*)d_in[2];
    const float* W2a = (const float*)d_in[3];
    const float* b1a = (const float*)d_in[4];
    const float* W1b = (const float*)d_in[5];
    const float* W2b = (const float*)d_in[6];
    const float* b1b = (const float*)d_in[7];
    const float* Wq = (const float*)d_in[8];
    const float* Wk = (const float*)d_in[9];
    const float* Wv = (const float*)d_in[10];
    const float* Wo = (const float*)d_in[11];
    const float* ln1g = (const float*)d_in[12];
    const float* ln1b = (const float*)d_in[13];
    const float* Wf1 = (const float*)d_in[14];
    const float* bf1 = (const float*)d_in[15];
    const float* Wf2 = (const float*)d_in[16];
    const float* bf2 = (const float*)d_in[17];
    const float* ln2g = (const float*)d_in[18];
    const float* ln2b = (const float*)d_in[19];
    const float* Wc = (const float*)d_in[20];
    const float* bc = (const float*)d_in[21];
    float* out = (float*)d_out;

    float *pWc1, *pW2ar, *pWc2, *pW2br, *pS, *pSdep, *pU1, *pH1, *pS1, *pU2, *pH2, *pg;
    float *pq, *pk, *pv, *patt, *ppart;
    cudaGetSymbolAddress((void**)&pWc1, g_Wc1);
    cudaGetSymbolAddress((void**)&pW2ar, g_W2ar);
    cudaGetSymbolAddress((void**)&pWc2, g_Wc2);
    cudaGetSymbolAddress((void**)&pW2br, g_W2br);
    cudaGetSymbolAddress((void**)&pS, g_S);
    cudaGetSymbolAddress((void**)&pSdep, g_Sdep);
    cudaGetSymbolAddress((void**)&pU1, g_U1);
    cudaGetSymbolAddress((void**)&pH1, g_H1);
    cudaGetSymbolAddress((void**)&pS1, g_S1);
    cudaGetSymbolAddress((void**)&pU2, g_U2);
    cudaGetSymbolAddress((void**)&pH2, g_H2);
    cudaGetSymbolAddress((void**)&pg, g_gp);
    cudaGetSymbolAddress((void**)&pq, g_q);
    cudaGetSymbolAddress((void**)&pk, g_k);
    cudaGetSymbolAddress((void**)&pv, g_v);
    cudaGetSymbolAddress((void**)&patt, g_att);
    cudaGetSymbolAddress((void**)&ppart, g_part);

    cudaFuncSetAttribute((const void*)gemm_tf32,
                         cudaFuncAttributeMaxDynamicSharedMemorySize, GEMM_SMEM);

    // combined + pre-rounded weights, neighbor sums
    prep_wc<<<1024, 256>>>(W1a, W2a, W1b, W2b);
    colsum30<<<dim3(cs_grid(K1), BT), 128>>>(feat, K1, pS, K1, 1.0f / (N_OBJ - 1));
    depsum<<<1, 256>>>(dep);

    // U1 = (S/29) @ W2a  (split-K=16, reduce adds Sdep rank-1 + b1a)
    {
        int planeStride = 2 * TBM * DH1;
        gemm_tf32<<<dim3(DH1 / TBN, 2, 16), 256, GEMM_SMEM>>>(
            pS, K1, pW2ar, DH1, ppart, DH1, planeStride, BT, DH1, K1,
            nullptr, nullptr, nullptr, nullptr, 0);
        splitk_reduce<<<(BT * DH1 + 255) / 256, 256>>>(
            ppart, 16, planeStride, pU1, BT, DH1,
            pSdep, W2a + (size_t)K1 * DH1, b1a);
    }

    // H1 = relu(X @ Wc1 + depth*Wc1row4096 + U1[bt])
    gemm_tf32<<<dim3(DH1 / TBN, (MROWS + TBM - 1) / TBM, 1), 256, GEMM_SMEM>>>(
        feat, K1, pWc1, DH1, pH1, DH1, 0, MROWS, DH1, K1,
        dep, pWc1 + (size_t)K1 * DH1, pU1, nullptr, 1);

    // layer b
    colsum30<<<dim3(cs_grid(DH1), BT), 128>>>(pH1, DH1, pS1, DH1, 1.0f / (N_OBJ - 1));
    {
        int planeStride = 2 * TBM * DH2;
        gemm_tf32<<<dim3(DH2 / TBN, 2, 8), 256, GEMM_SMEM>>>(
            pS1, DH1, pW2br, DH2, ppart, DH2, planeStride, BT, DH2, DH1,
            nullptr, nullptr, nullptr, nullptr, 0);
        splitk_reduce<<<(BT * DH2 + 255) / 256, 256>>>(
            ppart, 8, planeStride, pU2, BT, DH2, nullptr, nullptr, b1b);
    }
    gemm_tf32<<<dim3(DH2 / TBN, (MROWS + TBM - 1) / TBM, 1), 256, GEMM_SMEM>>>(
        pH1, DH1, pWc2, DH2, pH2, DH2, 0, MROWS, DH2, DH1,
        nullptr, nullptr, pU2, nullptr, 1);

    // pool
    colsum30<<<dim3(cs_grid(DH2), BT), 128>>>(pH2, DH2, pg, DH2, 1.0f / N_OBJ);

    // transformer (fused)
    qkv_kernel<<<BT, 256>>>(pg, Wq, Wk, Wv, pq, pk, pv);
    attn_kernel<<<dim3(T_LEN, BSZ_B * NH), 128>>>(pq, pk, pv, patt);
    tail_kernel<<<BT, 256>>>(patt, pg, Wo, ln1g, ln1b, Wf1, bf1, Wf2, bf2,
                             ln2g, ln2b, Wc, bc, out);

    if (out_size > BT) {
        int rem = out_size - BT;
        zerofill<<<(rem + 255) / 256, 256>>>(out + BT, rem);
    }
}